// round 8
// baseline (speedup 1.0000x reference)
#include <cuda_runtime.h>
#include <cuda_fp16.h>

#define NN 50000
#define EE 800000
#define ET 850000          // EE + NN self loops
#define GG 50
#define FIN 64
#define HID 128
#define EMB 64
#define H1 8
#define C1 16
#define NCLS 6
#define EPSV 1e-5f
#define SLOPE 0.2f
#define NB 196

// ---------------- scratch ----------------
__device__ int    g_ideg[NN], g_fill[NN], g_rowstart[NN];
__device__ int2   g_edge[ET];          // {src, attr bits}
__device__ float  g_asum[NN];
__device__ __half g_xl1h[NN * HID];
__device__ float  g_xr1[NN * HID], g_out1[NN * HID];
__device__ float  g_xl2[NN * EMB], g_xr2[NN * EMB], g_out2[NN * EMB];
__device__ float  g_bnsum[HID], g_bnsq[HID];
__device__ float  g_bnsum2[EMB], g_bnsq2[EMB];
__device__ float  g_pool[GG * EMB], g_cnt[GG];
__device__ int    g_done;

// ---------------- streams (static init; no device memory alloc) ----------------
static cudaStream_t g_side = nullptr;
static cudaEvent_t g_evF = nullptr, g_evJ = nullptr;
static struct SInit {
    SInit() {
        if (cudaStreamCreateWithFlags(&g_side, cudaStreamNonBlocking) != cudaSuccess) {
            g_side = nullptr; return;
        }
        if (cudaEventCreateWithFlags(&g_evF, cudaEventDisableTiming) != cudaSuccess ||
            cudaEventCreateWithFlags(&g_evJ, cudaEventDisableTiming) != cudaSuccess) {
            g_side = nullptr;
        }
    }
} s_init;

// ---------------- f32x2 helpers ----------------
__device__ __forceinline__ unsigned long long fma2v(unsigned long long a,
                                                    unsigned long long b,
                                                    unsigned long long c) {
    unsigned long long d;
    asm("fma.rn.f32x2 %0, %1, %2, %3;" : "=l"(d) : "l"(a), "l"(b), "l"(c));
    return d;
}
__device__ __forceinline__ unsigned long long pack2(float lo, float hi) {
    unsigned long long d;
    asm("mov.b64 %0, {%1, %2};" : "=l"(d) : "r"(__float_as_uint(lo)), "r"(__float_as_uint(hi)));
    return d;
}
__device__ __forceinline__ void unpack2(unsigned long long v, float& lo, float& hi) {
    unsigned int a, b;
    asm("mov.b64 {%0, %1}, %2;" : "=r"(a), "=r"(b) : "l"(v));
    lo = __uint_as_float(a); hi = __uint_as_float(b);
}

// ---------------- setup kernels ----------------
__global__ void k_zero() {
    int i = blockIdx.x * blockDim.x + threadIdx.x;
    if (i < NN) { g_ideg[i] = 0; g_fill[i] = 0; g_asum[i] = 0.f; }
    if (i < HID) { g_bnsum[i] = 0.f; g_bnsq[i] = 0.f; }
    if (i < EMB) { g_bnsum2[i] = 0.f; g_bnsq2[i] = 0.f; }
    if (i < GG * EMB) g_pool[i] = 0.f;
    if (i < GG) g_cnt[i] = 0.f;
    if (i == 0) g_done = 0;
}

__global__ void k_hist(const int* __restrict__ dst, const float* __restrict__ eattr) {
    int i = blockIdx.x * blockDim.x + threadIdx.x;
    if (i >= EE) return;
    int d = dst[i];
    atomicAdd(&g_ideg[d], 1);
    atomicAdd(&g_asum[d], eattr[i]);
}

// single-block scan: rowstart + self-loop record + batch counts
__global__ void k_scan(const int* __restrict__ batch) {
    __shared__ int wsum[32];
    __shared__ int carry;
    int t = threadIdx.x, lane = t & 31, wid = t >> 5;
    if (t == 0) carry = 0;
    __syncthreads();
    for (int base = 0; base < NN; base += 1024) {
        int i = base + t;
        int deg = (i < NN) ? g_ideg[i] : 0;
        int v = (i < NN) ? deg + 1 : 0;
        int x = v;
#pragma unroll
        for (int off = 1; off < 32; off <<= 1) {
            int y = __shfl_up_sync(0xffffffffu, x, off);
            if (lane >= off) x += y;
        }
        if (lane == 31) wsum[wid] = x;
        __syncthreads();
        if (wid == 0) {
            int ws = wsum[lane];
            int wx = ws;
#pragma unroll
            for (int off = 1; off < 32; off <<= 1) {
                int y = __shfl_up_sync(0xffffffffu, wx, off);
                if (lane >= off) wx += y;
            }
            wsum[lane] = wx - ws;     // exclusive warp offsets
        }
        __syncthreads();
        int ex = carry + wsum[wid] + (x - v);
        if (i < NN) {
            g_rowstart[i] = ex;
            float la = deg > 0 ? g_asum[i] / (float)deg : 0.f;
            g_edge[ex + deg] = make_int2(i, __float_as_int(la));   // self loop last
            atomicAdd(&g_cnt[batch[i]], 1.f);
        }
        __syncthreads();
        if (t == 1023) carry += wsum[31] + x;
        __syncthreads();
    }
}

__global__ void k_scatterE(const int* __restrict__ src, const int* __restrict__ dst,
                           const float* __restrict__ eattr) {
    int e = blockIdx.x * blockDim.x + threadIdx.x;
    if (e >= EE) return;
    int d = dst[e];
    int pos = g_rowstart[d] + atomicAdd(&g_fill[d], 1);
    g_edge[pos] = make_int2(src[e], __float_as_int(eattr[e]));
}

// ---------------- GEMM: BM=128, BN=64, 8x4/thread, KTILE=32, FFMA2 ----------
// X tile stored k-major + swizzled so row-pairs load as packed f32x2 operands.
// BNF: X passes relu(x*scale+shift) (fused BN1). HOUT: Y1 written fp16.
template<int KIN, bool BNF, bool HOUT>
__global__ void k_gemm(const float* __restrict__ X,
                       const float* __restrict__ W1, const float* __restrict__ b1,
                       float* __restrict__ Y1, __half* __restrict__ Y1h,
                       const float* __restrict__ W2, const float* __restrict__ b2,
                       float* __restrict__ Y2,
                       int kout, int tiles1,
                       const float* __restrict__ gamma, const float* __restrict__ beta) {
    __shared__ float XsT[32 * 132];    // [k][swizzled row]
    __shared__ float Ws[32][68];
    __shared__ float sscale[KIN], sshift[KIN];
    int tid = threadIdx.x;
    if (BNF) {
        if (tid < KIN) {
            float mu = g_bnsum[tid] * (1.f / NN);
            float var = g_bnsq[tid] * (1.f / NN) - mu * mu;
            float sc = gamma[tid] * rsqrtf(var + EPSV);
            sscale[tid] = sc;
            sshift[tid] = beta[tid] - mu * sc;
        }
        __syncthreads();
    }
    int yt = blockIdx.y;
    bool first = yt < tiles1;
    const float* W; const float* bb; int colbase;
    if (first) { W = W1; bb = b1; colbase = yt * 64; }
    else       { W = W2; bb = b2; colbase = (yt - tiles1) * 64; }

    int tx = tid & 15, ty = tid >> 4;
    int r0 = blockIdx.x * 128;
    unsigned long long accP[4][4] = {};   // [row pair][col], packed f32x2

#pragma unroll
    for (int kt = 0; kt < KIN / 32; kt++) {
        // -- load X tile transposed + swizzled --
#pragma unroll
        for (int it = 0; it < 4; it++) {
            int idx = tid + it * 256;
            int row = idx >> 3;
            int m = idx & 7;              // = k>>2 for this thread's 4 k's
            int kc4 = m * 4;
            int grow = r0 + row;
            float4 v = {0.f, 0.f, 0.f, 0.f};
            if (grow < NN)
                v = *(const float4*)(X + (size_t)grow * KIN + kt * 32 + kc4);
            if (BNF) {
                int kc = kt * 32 + kc4;
                v.x = fmaxf(fmaf(v.x, sscale[kc + 0], sshift[kc + 0]), 0.f);
                v.y = fmaxf(fmaf(v.y, sscale[kc + 1], sshift[kc + 1]), 0.f);
                v.z = fmaxf(fmaf(v.z, sscale[kc + 2], sshift[kc + 2]), 0.f);
                v.w = fmaxf(fmaf(v.w, sscale[kc + 3], sshift[kc + 3]), 0.f);
            }
            int pb = ((row >> 3) ^ m) & 15;
            int r7 = (row & 7) ^ ((m & 4) ? 4 : 0);
            int off = pb * 8 + r7;
            XsT[(kc4 + 0) * 132 + off] = v.x;
            XsT[(kc4 + 1) * 132 + off] = v.y;
            XsT[(kc4 + 2) * 132 + off] = v.z;
            XsT[(kc4 + 3) * 132 + off] = v.w;
        }
#pragma unroll
        for (int it = 0; it < 2; it++) {
            int idx = tid + it * 256;
            int k = idx >> 4, c4 = (idx & 15) * 4;
            float4 v = *(const float4*)(W + (size_t)(kt * 32 + k) * kout + colbase + c4);
            *(float4*)&Ws[k][c4] = v;
        }
        __syncthreads();
#pragma unroll
        for (int k = 0; k < 32; k++) {
            int m = k >> 2;
            int pb = (ty ^ m) & 15;
            const ulonglong2* pA = (const ulonglong2*)&XsT[k * 132 + pb * 8];
            ulonglong2 lo = pA[0];
            ulonglong2 hi = pA[1];
            if (k & 16) { ulonglong2 tsw = lo; lo = hi; hi = tsw; }
            float4 bv = *(float4*)&Ws[k][tx * 4];
            unsigned long long bx = pack2(bv.x, bv.x);
            unsigned long long by = pack2(bv.y, bv.y);
            unsigned long long bz = pack2(bv.z, bv.z);
            unsigned long long bw = pack2(bv.w, bv.w);
            accP[0][0] = fma2v(lo.x, bx, accP[0][0]);
            accP[0][1] = fma2v(lo.x, by, accP[0][1]);
            accP[0][2] = fma2v(lo.x, bz, accP[0][2]);
            accP[0][3] = fma2v(lo.x, bw, accP[0][3]);
            accP[1][0] = fma2v(lo.y, bx, accP[1][0]);
            accP[1][1] = fma2v(lo.y, by, accP[1][1]);
            accP[1][2] = fma2v(lo.y, bz, accP[1][2]);
            accP[1][3] = fma2v(lo.y, bw, accP[1][3]);
            accP[2][0] = fma2v(hi.x, bx, accP[2][0]);
            accP[2][1] = fma2v(hi.x, by, accP[2][1]);
            accP[2][2] = fma2v(hi.x, bz, accP[2][2]);
            accP[2][3] = fma2v(hi.x, bw, accP[2][3]);
            accP[3][0] = fma2v(hi.y, bx, accP[3][0]);
            accP[3][1] = fma2v(hi.y, by, accP[3][1]);
            accP[3][2] = fma2v(hi.y, bz, accP[3][2]);
            accP[3][3] = fma2v(hi.y, bw, accP[3][3]);
        }
        __syncthreads();
    }
    float4 bias = *(const float4*)(bb + colbase + tx * 4);
#pragma unroll
    for (int p = 0; p < 4; p++) {
        float e0[4], e1[4];
#pragma unroll
        for (int j = 0; j < 4; j++) unpack2(accP[p][j], e0[j], e1[j]);
        int row = r0 + ty * 8 + 2 * p;
#pragma unroll
        for (int h = 0; h < 2; h++) {
            int rr = row + h;
            if (rr < NN) {
                const float* ev = h ? e1 : e0;
                float4 o = {ev[0] + bias.x, ev[1] + bias.y, ev[2] + bias.z, ev[3] + bias.w};
                if (HOUT && first) {
                    __half2 h01 = __floats2half2_rn(o.x, o.y);
                    __half2 h23 = __floats2half2_rn(o.z, o.w);
                    __half2* pp = (__half2*)(Y1h + (size_t)rr * kout + colbase + tx * 4);
                    pp[0] = h01; pp[1] = h23;
                } else {
                    float* Y = first ? Y1 : Y2;
                    *(float4*)(Y + (size_t)rr * kout + colbase + tx * 4) = o;
                }
            }
        }
    }
}

// ---------------- fused GATv2 aggregation + BN stats: warp/node, 4-edge batch ----
__device__ __forceinline__ void xl1_load(int s, int c0, float4& f) {
    uint2 raw = *(const uint2*)(g_xl1h + (size_t)s * HID + c0);
    float2 f01 = __half22float2(*(__half2*)&raw.x);
    float2 f23 = __half22float2(*(__half2*)&raw.y);
    f.x = f01.x; f.y = f01.y; f.z = f23.x; f.w = f23.y;
}

__global__ void k_agg1(const float* __restrict__ We, const float* __restrict__ att) {
    __shared__ float ssum[HID], ssq[HID];
    int t = threadIdx.x;
    if (t < HID) { ssum[t] = 0.f; ssq[t] = 0.f; }
    __syncthreads();
    int n = (blockIdx.x * blockDim.x + t) >> 5;
    int lane = t & 31;
    int start = g_rowstart[n];
    int end = start + g_ideg[n] + 1;
    int c0 = lane * 4;
    float4 xr = *(const float4*)(g_xr1 + (size_t)n * HID + c0);
    float4 we = *(const float4*)(We + c0);
    int h = lane >> 2;
    float4 at = *(const float4*)(att + h * C1 + (lane & 3) * 4);
    float4 numA = {0.f, 0.f, 0.f, 0.f}, numB = {0.f, 0.f, 0.f, 0.f};
    float denA = 0.f, denB = 0.f;
    int e = start;
    for (; e + 3 < end; e += 4) {
        int2 e0 = g_edge[e], e1 = g_edge[e + 1], e2i = g_edge[e + 2], e3i = g_edge[e + 3];
        float a0 = __int_as_float(e0.y), a1 = __int_as_float(e1.y);
        float a2 = __int_as_float(e2i.y), a3 = __int_as_float(e3i.y);
        float4 x0, x1, x2, x3;
        xl1_load(e0.x, c0, x0);
        xl1_load(e1.x, c0, x1);
        xl1_load(e2i.x, c0, x2);
        xl1_load(e3i.x, c0, x3);
        float u0, u1, u2, u3;
        u0 = x0.x + xr.x + a0 * we.x; u0 = u0 > 0.f ? u0 : SLOPE * u0;
        u1 = x0.y + xr.y + a0 * we.y; u1 = u1 > 0.f ? u1 : SLOPE * u1;
        u2 = x0.z + xr.z + a0 * we.z; u2 = u2 > 0.f ? u2 : SLOPE * u2;
        u3 = x0.w + xr.w + a0 * we.w; u3 = u3 > 0.f ? u3 : SLOPE * u3;
        float p0 = u0 * at.x + u1 * at.y + u2 * at.z + u3 * at.w;
        u0 = x1.x + xr.x + a1 * we.x; u0 = u0 > 0.f ? u0 : SLOPE * u0;
        u1 = x1.y + xr.y + a1 * we.y; u1 = u1 > 0.f ? u1 : SLOPE * u1;
        u2 = x1.z + xr.z + a1 * we.z; u2 = u2 > 0.f ? u2 : SLOPE * u2;
        u3 = x1.w + xr.w + a1 * we.w; u3 = u3 > 0.f ? u3 : SLOPE * u3;
        float p1 = u0 * at.x + u1 * at.y + u2 * at.z + u3 * at.w;
        u0 = x2.x + xr.x + a2 * we.x; u0 = u0 > 0.f ? u0 : SLOPE * u0;
        u1 = x2.y + xr.y + a2 * we.y; u1 = u1 > 0.f ? u1 : SLOPE * u1;
        u2 = x2.z + xr.z + a2 * we.z; u2 = u2 > 0.f ? u2 : SLOPE * u2;
        u3 = x2.w + xr.w + a2 * we.w; u3 = u3 > 0.f ? u3 : SLOPE * u3;
        float p2 = u0 * at.x + u1 * at.y + u2 * at.z + u3 * at.w;
        u0 = x3.x + xr.x + a3 * we.x; u0 = u0 > 0.f ? u0 : SLOPE * u0;
        u1 = x3.y + xr.y + a3 * we.y; u1 = u1 > 0.f ? u1 : SLOPE * u1;
        u2 = x3.z + xr.z + a3 * we.z; u2 = u2 > 0.f ? u2 : SLOPE * u2;
        u3 = x3.w + xr.w + a3 * we.w; u3 = u3 > 0.f ? u3 : SLOPE * u3;
        float p3 = u0 * at.x + u1 * at.y + u2 * at.z + u3 * at.w;
        p0 += __shfl_xor_sync(0xffffffffu, p0, 1);
        p1 += __shfl_xor_sync(0xffffffffu, p1, 1);
        p2 += __shfl_xor_sync(0xffffffffu, p2, 1);
        p3 += __shfl_xor_sync(0xffffffffu, p3, 1);
        p0 += __shfl_xor_sync(0xffffffffu, p0, 2);
        p1 += __shfl_xor_sync(0xffffffffu, p1, 2);
        p2 += __shfl_xor_sync(0xffffffffu, p2, 2);
        p3 += __shfl_xor_sync(0xffffffffu, p3, 2);
        float w0 = __expf(p0), w1 = __expf(p1), w2 = __expf(p2), w3 = __expf(p3);
        denA += w0 + w2; denB += w1 + w3;
        numA.x = fmaf(w0, x0.x, fmaf(w2, x2.x, numA.x));
        numA.y = fmaf(w0, x0.y, fmaf(w2, x2.y, numA.y));
        numA.z = fmaf(w0, x0.z, fmaf(w2, x2.z, numA.z));
        numA.w = fmaf(w0, x0.w, fmaf(w2, x2.w, numA.w));
        numB.x = fmaf(w1, x1.x, fmaf(w3, x3.x, numB.x));
        numB.y = fmaf(w1, x1.y, fmaf(w3, x3.y, numB.y));
        numB.z = fmaf(w1, x1.z, fmaf(w3, x3.z, numB.z));
        numB.w = fmaf(w1, x1.w, fmaf(w3, x3.w, numB.w));
    }
    for (; e < end; e++) {
        int2 er = g_edge[e];
        float a0 = __int_as_float(er.y);
        float4 x0; xl1_load(er.x, c0, x0);
        float u0, u1, u2, u3;
        u0 = x0.x + xr.x + a0 * we.x; u0 = u0 > 0.f ? u0 : SLOPE * u0;
        u1 = x0.y + xr.y + a0 * we.y; u1 = u1 > 0.f ? u1 : SLOPE * u1;
        u2 = x0.z + xr.z + a0 * we.z; u2 = u2 > 0.f ? u2 : SLOPE * u2;
        u3 = x0.w + xr.w + a0 * we.w; u3 = u3 > 0.f ? u3 : SLOPE * u3;
        float p0 = u0 * at.x + u1 * at.y + u2 * at.z + u3 * at.w;
        p0 += __shfl_xor_sync(0xffffffffu, p0, 1);
        p0 += __shfl_xor_sync(0xffffffffu, p0, 2);
        float w0 = __expf(p0);
        denA += w0;
        numA.x = fmaf(w0, x0.x, numA.x); numA.y = fmaf(w0, x0.y, numA.y);
        numA.z = fmaf(w0, x0.z, numA.z); numA.w = fmaf(w0, x0.w, numA.w);
    }
    float inv = 1.f / (denA + denB);
    float4 o = {(numA.x + numB.x) * inv, (numA.y + numB.y) * inv,
                (numA.z + numB.z) * inv, (numA.w + numB.w) * inv};
    *(float4*)(g_out1 + (size_t)n * HID + c0) = o;
    atomicAdd(&ssum[c0 + 0], o.x); atomicAdd(&ssq[c0 + 0], o.x * o.x);
    atomicAdd(&ssum[c0 + 1], o.y); atomicAdd(&ssq[c0 + 1], o.y * o.y);
    atomicAdd(&ssum[c0 + 2], o.z); atomicAdd(&ssq[c0 + 2], o.z * o.z);
    atomicAdd(&ssum[c0 + 3], o.w); atomicAdd(&ssq[c0 + 3], o.w * o.w);
    __syncthreads();
    if (t < HID) { atomicAdd(&g_bnsum[t], ssum[t]); atomicAdd(&g_bnsq[t], ssq[t]); }
}

__global__ void k_agg2(const float* __restrict__ We, const float* __restrict__ att) {
    __shared__ float ssum[EMB], ssq[EMB];
    int t = threadIdx.x;
    if (t < EMB) { ssum[t] = 0.f; ssq[t] = 0.f; }
    __syncthreads();
    int n = (blockIdx.x * blockDim.x + t) >> 5;
    int lane = t & 31;
    int start = g_rowstart[n];
    int end = start + g_ideg[n] + 1;
    int c0 = lane * 2;
    float2 xr = *(const float2*)(g_xr2 + (size_t)n * EMB + c0);
    float2 we = *(const float2*)(We + c0);
    float2 at = *(const float2*)(att + c0);
    float2 numA = {0.f, 0.f}, numB = {0.f, 0.f};
    float denA = 0.f, denB = 0.f;
    int e = start;
    for (; e + 3 < end; e += 4) {
        int2 e0 = g_edge[e], e1 = g_edge[e + 1], e2i = g_edge[e + 2], e3i = g_edge[e + 3];
        float a0 = __int_as_float(e0.y), a1 = __int_as_float(e1.y);
        float a2 = __int_as_float(e2i.y), a3 = __int_as_float(e3i.y);
        float2 x0 = *(const float2*)(g_xl2 + (size_t)e0.x * EMB + c0);
        float2 x1 = *(const float2*)(g_xl2 + (size_t)e1.x * EMB + c0);
        float2 x2 = *(const float2*)(g_xl2 + (size_t)e2i.x * EMB + c0);
        float2 x3 = *(const float2*)(g_xl2 + (size_t)e3i.x * EMB + c0);
        float u0, u1;
        u0 = x0.x + xr.x + a0 * we.x; u0 = u0 > 0.f ? u0 : SLOPE * u0;
        u1 = x0.y + xr.y + a0 * we.y; u1 = u1 > 0.f ? u1 : SLOPE * u1;
        float p0 = u0 * at.x + u1 * at.y;
        u0 = x1.x + xr.x + a1 * we.x; u0 = u0 > 0.f ? u0 : SLOPE * u0;
        u1 = x1.y + xr.y + a1 * we.y; u1 = u1 > 0.f ? u1 : SLOPE * u1;
        float p1 = u0 * at.x + u1 * at.y;
        u0 = x2.x + xr.x + a2 * we.x; u0 = u0 > 0.f ? u0 : SLOPE * u0;
        u1 = x2.y + xr.y + a2 * we.y; u1 = u1 > 0.f ? u1 : SLOPE * u1;
        float p2 = u0 * at.x + u1 * at.y;
        u0 = x3.x + xr.x + a3 * we.x; u0 = u0 > 0.f ? u0 : SLOPE * u0;
        u1 = x3.y + xr.y + a3 * we.y; u1 = u1 > 0.f ? u1 : SLOPE * u1;
        float p3 = u0 * at.x + u1 * at.y;
#pragma unroll
        for (int off = 16; off > 0; off >>= 1) {
            p0 += __shfl_xor_sync(0xffffffffu, p0, off);
            p1 += __shfl_xor_sync(0xffffffffu, p1, off);
            p2 += __shfl_xor_sync(0xffffffffu, p2, off);
            p3 += __shfl_xor_sync(0xffffffffu, p3, off);
        }
        float w0 = __expf(p0), w1 = __expf(p1), w2 = __expf(p2), w3 = __expf(p3);
        denA += w0 + w2; denB += w1 + w3;
        numA.x = fmaf(w0, x0.x, fmaf(w2, x2.x, numA.x));
        numA.y = fmaf(w0, x0.y, fmaf(w2, x2.y, numA.y));
        numB.x = fmaf(w1, x1.x, fmaf(w3, x3.x, numB.x));
        numB.y = fmaf(w1, x1.y, fmaf(w3, x3.y, numB.y));
    }
    for (; e < end; e++) {
        int2 er = g_edge[e];
        float a0 = __int_as_float(er.y);
        float2 x0 = *(const float2*)(g_xl2 + (size_t)er.x * EMB + c0);
        float u0, u1;
        u0 = x0.x + xr.x + a0 * we.x; u0 = u0 > 0.f ? u0 : SLOPE * u0;
        u1 = x0.y + xr.y + a0 * we.y; u1 = u1 > 0.f ? u1 : SLOPE * u1;
        float p0 = u0 * at.x + u1 * at.y;
#pragma unroll
        for (int off = 16; off > 0; off >>= 1)
            p0 += __shfl_xor_sync(0xffffffffu, p0, off);
        float w0 = __expf(p0);
        denA += w0;
        numA.x = fmaf(w0, x0.x, numA.x); numA.y = fmaf(w0, x0.y, numA.y);
    }
    float inv = 1.f / (denA + denB);
    float2 o = {(numA.x + numB.x) * inv, (numA.y + numB.y) * inv};
    *(float2*)(g_out2 + (size_t)n * EMB + c0) = o;
    atomicAdd(&ssum[c0 + 0], o.x); atomicAdd(&ssq[c0 + 0], o.x * o.x);
    atomicAdd(&ssum[c0 + 1], o.y); atomicAdd(&ssq[c0 + 1], o.y * o.y);
    __syncthreads();
    if (t < EMB) { atomicAdd(&g_bnsum2[t], ssum[t]); atomicAdd(&g_bnsq2[t], ssq[t]); }
}

// BN2(inline) + relu + node_emb + pooled sums; last block finishes pool+logits
__global__ void k_bnapply2(const float* __restrict__ Yin, float* __restrict__ out,
                           const int* __restrict__ batch,
                           const float* __restrict__ gamma, const float* __restrict__ beta,
                           const float* __restrict__ Wc, const float* __restrict__ bc) {
    int i = blockIdx.x * 256 + threadIdx.x;   // grid covers NN*EMB exactly
    int c = i & (EMB - 1);
    int node = i >> 6;
    float mu = g_bnsum2[c] * (1.f / NN);
    float var = g_bnsq2[c] * (1.f / NN) - mu * mu;
    float sc = gamma[c] * rsqrtf(var + EPSV);
    float v = fmaf(Yin[i] - mu, sc, beta[c]);
    v = fmaxf(v, 0.f);
    out[NCLS * GG + GG * EMB + i] = v;        // node_emb
    atomicAdd(&g_pool[batch[node] * EMB + c], v);

    __threadfence();
    __shared__ int lastblk;
    __shared__ float sdom[GG * EMB];
    if (threadIdx.x == 0)
        lastblk = (atomicAdd(&g_done, 1) == (NN * EMB) / 256 - 1);
    __syncthreads();
    if (!lastblk) return;
    for (int p = threadIdx.x; p < GG * EMB; p += 256) {
        int g = p >> 6;
        float dm = g_pool[p] / fmaxf(g_cnt[g], 1.f);
        sdom[p] = dm;
        out[NCLS * GG + p] = dm;              // domain_emb
    }
    __syncthreads();
    for (int p = threadIdx.x; p < GG * NCLS; p += 256) {   // FIX: 300 > 256
        int g = p / NCLS, cc = p % NCLS;
        float acc = bc[cc];
#pragma unroll 8
        for (int k = 0; k < EMB; k++)
            acc = fmaf(sdom[g * EMB + k], Wc[k * NCLS + cc], acc);
        out[p] = acc;                          // logits
    }
}

// ---------------- host ----------------
extern "C" void kernel_launch(void* const* d_in, const int* in_sizes, int n_in,
                              void* d_out, int out_size) {
    const float* x     = (const float*)d_in[0];
    const int*   ei    = (const int*)d_in[1];
    const float* eattr = (const float*)d_in[2];
    const int*   batch = (const int*)d_in[3];
    const float* Wl1 = (const float*)d_in[4];  const float* bl1 = (const float*)d_in[5];
    const float* Wr1 = (const float*)d_in[6];  const float* br1 = (const float*)d_in[7];
    const float* We1 = (const float*)d_in[8];  const float* att1 = (const float*)d_in[9];
    // bias1 (d_in[10]) cancels exactly through BN1 -> skipped
    const float* Wl2 = (const float*)d_in[11]; const float* bl2 = (const float*)d_in[12];
    const float* Wr2 = (const float*)d_in[13]; const float* br2 = (const float*)d_in[14];
    const float* We2 = (const float*)d_in[15]; const float* att2 = (const float*)d_in[16];
    // bias2 (d_in[17]) cancels through BN2 -> skipped
    const float* gamma1 = (const float*)d_in[18]; const float* beta1 = (const float*)d_in[19];
    const float* gamma2 = (const float*)d_in[20]; const float* beta2 = (const float*)d_in[21];
    const float* Wc = (const float*)d_in[22]; const float* bc = (const float*)d_in[23];
    float* out = (float*)d_out;

    float *xr1, *out1, *xl2, *xr2, *out2;
    __half* xl1h;
    cudaGetSymbolAddress((void**)&xl1h, g_xl1h);
    cudaGetSymbolAddress((void**)&xr1, g_xr1);
    cudaGetSymbolAddress((void**)&out1, g_out1);
    cudaGetSymbolAddress((void**)&xl2, g_xl2);
    cudaGetSymbolAddress((void**)&xr2, g_xr2);
    cudaGetSymbolAddress((void**)&out2, g_out2);

    const int* src = ei;
    const int* dst = ei + EE;

    bool par = (g_side != nullptr);

    // ---- fork: gemm1 runs concurrent with CSR build ----
    if (par) {
        cudaEventRecord(g_evF, 0);
        cudaStreamWaitEvent(g_side, g_evF, 0);
    }
    k_gemm<FIN, false, true><<<dim3(391, 4), 256, 0, par ? g_side : 0>>>(
        x, Wl1, bl1, nullptr, xl1h, Wr1, br1, xr1, HID, 2, nullptr, nullptr);
    if (par) cudaEventRecord(g_evJ, g_side);

    // ---- CSR build (main stream) ----
    k_zero<<<NB, 256>>>();
    k_hist<<<(EE + 255) / 256, 256>>>(dst, eattr);
    k_scan<<<1, 1024>>>(batch);
    k_scatterE<<<(EE + 255) / 256, 256>>>(src, dst, eattr);

    // ---- join ----
    if (par) cudaStreamWaitEvent(0, g_evJ, 0);

    // ---- layer 1 aggregation (+BN1 stats) ----
    k_agg1<<<6250, 256>>>(We1, att1);

    // ---- layer 2 (BN1+relu fused into GEMM X load) ----
    k_gemm<HID, true, false><<<dim3(391, 2), 256>>>(
        out1, Wl2, bl2, xl2, nullptr, Wr2, br2, xr2, EMB, 1, gamma1, beta1);
    k_agg2<<<6250, 256>>>(We2, att2);

    // ---- BN2 + pooling + classifier (fused tail) ----
    k_bnapply2<<<(NN * EMB) / 256, 256>>>(out2, out, batch, gamma2, beta2, Wc, bc);
}

// round 9
// speedup vs baseline: 1.1630x; 1.1630x over previous
#include <cuda_runtime.h>
#include <cuda_fp16.h>

#define NN 50000
#define EE 800000
#define ET 850000          // EE + NN self loops
#define GG 50
#define FIN 64
#define HID 128
#define EMB 64
#define H1 8
#define C1 16
#define NCLS 6
#define EPSV 1e-5f
#define SLOPE 0.2f
#define NB 196

// ---------------- scratch ----------------
__device__ int    g_ideg[NN], g_fill[NN], g_rowstart[NN];
__device__ int    g_psum[NB], g_poff[NB];
__device__ int2   g_edge[ET];          // {src, attr bits}
__device__ float  g_asum[NN];
__device__ __half g_xl1h[NN * HID];
__device__ float  g_xr1[NN * HID], g_out1[NN * HID];
__device__ float  g_xl2[NN * EMB], g_xr2[NN * EMB], g_out2[NN * EMB];
__device__ float  g_bnsum[HID], g_bnsq[HID];
__device__ float  g_bnsum2[EMB], g_bnsq2[EMB];
__device__ float  g_pool[GG * EMB], g_cnt[GG];
__device__ int    g_done;

// ---------------- streams (static init; no device memory alloc) ----------------
static cudaStream_t g_side = nullptr;
static cudaEvent_t g_evF = nullptr, g_evJ = nullptr;
static struct SInit {
    SInit() {
        if (cudaStreamCreateWithFlags(&g_side, cudaStreamNonBlocking) != cudaSuccess) {
            g_side = nullptr; return;
        }
        if (cudaEventCreateWithFlags(&g_evF, cudaEventDisableTiming) != cudaSuccess ||
            cudaEventCreateWithFlags(&g_evJ, cudaEventDisableTiming) != cudaSuccess) {
            g_side = nullptr;
        }
    }
} s_init;

// ---------------- f32x2 helpers ----------------
__device__ __forceinline__ unsigned long long fma2v(unsigned long long a,
                                                    unsigned long long b,
                                                    unsigned long long c) {
    unsigned long long d;
    asm("fma.rn.f32x2 %0, %1, %2, %3;" : "=l"(d) : "l"(a), "l"(b), "l"(c));
    return d;
}
__device__ __forceinline__ unsigned long long pack2(float lo, float hi) {
    unsigned long long d;
    asm("mov.b64 %0, {%1, %2};" : "=l"(d) : "r"(__float_as_uint(lo)), "r"(__float_as_uint(hi)));
    return d;
}
__device__ __forceinline__ void unpack2(unsigned long long v, float& lo, float& hi) {
    unsigned int a, b;
    asm("mov.b64 {%0, %1}, %2;" : "=r"(a), "=r"(b) : "l"(v));
    lo = __uint_as_float(a); hi = __uint_as_float(b);
}

// ---------------- setup kernels ----------------
__global__ void k_zero() {
    int i = blockIdx.x * blockDim.x + threadIdx.x;
    if (i < NN) { g_ideg[i] = 0; g_fill[i] = 0; g_asum[i] = 0.f; }
    if (i < HID) { g_bnsum[i] = 0.f; g_bnsq[i] = 0.f; }
    if (i < EMB) { g_bnsum2[i] = 0.f; g_bnsq2[i] = 0.f; }
    if (i < GG * EMB) g_pool[i] = 0.f;
    if (i < GG) g_cnt[i] = 0.f;
    if (i == 0) g_done = 0;
}

__global__ void k_hist(const int* __restrict__ dst, const float* __restrict__ eattr) {
    int i = blockIdx.x * blockDim.x + threadIdx.x;
    if (i >= EE) return;
    int d = dst[i];
    atomicAdd(&g_ideg[d], 1);
    atomicAdd(&g_asum[d], eattr[i]);
}

__global__ void k_scanA() {
    __shared__ int s[256];
    int i = blockIdx.x * 256 + threadIdx.x;
    int v = (i < NN) ? g_ideg[i] + 1 : 0;
    s[threadIdx.x] = v; __syncthreads();
    for (int off = 128; off > 0; off >>= 1) {
        if (threadIdx.x < off) s[threadIdx.x] += s[threadIdx.x + off];
        __syncthreads();
    }
    if (threadIdx.x == 0) g_psum[blockIdx.x] = s[0];
}

__global__ void k_scanB() {
    __shared__ int s[256];
    int t = threadIdx.x;
    int v = (t < NB) ? g_psum[t] : 0;
    s[t] = v; __syncthreads();
    for (int off = 1; off < 256; off <<= 1) {
        int x = (t >= off) ? s[t - off] : 0;
        __syncthreads();
        s[t] += x;
        __syncthreads();
    }
    if (t < NB) g_poff[t] = s[t] - v;
}

// per-block exclusive scan + rowstart + self-loop record + batch counts
__global__ void k_scanC(const int* __restrict__ batch) {
    __shared__ int s[256];
    int t = threadIdx.x;
    int i = blockIdx.x * 256 + t;
    int deg = (i < NN) ? g_ideg[i] : 0;
    int v = (i < NN) ? deg + 1 : 0;
    s[t] = v; __syncthreads();
    for (int off = 1; off < 256; off <<= 1) {
        int x = (t >= off) ? s[t - off] : 0;
        __syncthreads();
        s[t] += x;
        __syncthreads();
    }
    if (i < NN) {
        int rs = g_poff[blockIdx.x] + s[t] - v;
        g_rowstart[i] = rs;
        float la = deg > 0 ? g_asum[i] / (float)deg : 0.f;
        g_edge[rs + deg] = make_int2(i, __float_as_int(la));   // self loop last
        atomicAdd(&g_cnt[batch[i]], 1.f);
    }
}

__global__ void k_scatterE(const int* __restrict__ src, const int* __restrict__ dst,
                           const float* __restrict__ eattr) {
    int e = blockIdx.x * blockDim.x + threadIdx.x;
    if (e >= EE) return;
    int d = dst[e];
    int pos = g_rowstart[d] + atomicAdd(&g_fill[d], 1);
    g_edge[pos] = make_int2(src[e], __float_as_int(eattr[e]));
}

// ---------------- GEMM: BM=128, BN=64, 8x4/thread, KTILE=32, FFMA2 ----------
template<int KIN, bool BNF, bool HOUT>
__global__ void k_gemm(const float* __restrict__ X,
                       const float* __restrict__ W1, const float* __restrict__ b1,
                       float* __restrict__ Y1, __half* __restrict__ Y1h,
                       const float* __restrict__ W2, const float* __restrict__ b2,
                       float* __restrict__ Y2,
                       int kout, int tiles1,
                       const float* __restrict__ gamma, const float* __restrict__ beta) {
    __shared__ float XsT[32 * 132];    // [k][swizzled row]
    __shared__ float Ws[32][68];
    __shared__ float sscale[KIN], sshift[KIN];
    int tid = threadIdx.x;
    if (BNF) {
        if (tid < KIN) {
            float mu = g_bnsum[tid] * (1.f / NN);
            float var = g_bnsq[tid] * (1.f / NN) - mu * mu;
            float sc = gamma[tid] * rsqrtf(var + EPSV);
            sscale[tid] = sc;
            sshift[tid] = beta[tid] - mu * sc;
        }
        __syncthreads();
    }
    int yt = blockIdx.y;
    bool first = yt < tiles1;
    const float* W; const float* bb; int colbase;
    if (first) { W = W1; bb = b1; colbase = yt * 64; }
    else       { W = W2; bb = b2; colbase = (yt - tiles1) * 64; }

    int tx = tid & 15, ty = tid >> 4;
    int r0 = blockIdx.x * 128;
    unsigned long long accP[4][4] = {};   // [row pair][col], packed f32x2

#pragma unroll
    for (int kt = 0; kt < KIN / 32; kt++) {
#pragma unroll
        for (int it = 0; it < 4; it++) {
            int idx = tid + it * 256;
            int row = idx >> 3;
            int m = idx & 7;
            int kc4 = m * 4;
            int grow = r0 + row;
            float4 v = {0.f, 0.f, 0.f, 0.f};
            if (grow < NN)
                v = *(const float4*)(X + (size_t)grow * KIN + kt * 32 + kc4);
            if (BNF) {
                int kc = kt * 32 + kc4;
                v.x = fmaxf(fmaf(v.x, sscale[kc + 0], sshift[kc + 0]), 0.f);
                v.y = fmaxf(fmaf(v.y, sscale[kc + 1], sshift[kc + 1]), 0.f);
                v.z = fmaxf(fmaf(v.z, sscale[kc + 2], sshift[kc + 2]), 0.f);
                v.w = fmaxf(fmaf(v.w, sscale[kc + 3], sshift[kc + 3]), 0.f);
            }
            int pb = ((row >> 3) ^ m) & 15;
            int r7 = (row & 7) ^ ((m & 4) ? 4 : 0);
            int off = pb * 8 + r7;
            XsT[(kc4 + 0) * 132 + off] = v.x;
            XsT[(kc4 + 1) * 132 + off] = v.y;
            XsT[(kc4 + 2) * 132 + off] = v.z;
            XsT[(kc4 + 3) * 132 + off] = v.w;
        }
#pragma unroll
        for (int it = 0; it < 2; it++) {
            int idx = tid + it * 256;
            int k = idx >> 4, c4 = (idx & 15) * 4;
            float4 v = *(const float4*)(W + (size_t)(kt * 32 + k) * kout + colbase + c4);
            *(float4*)&Ws[k][c4] = v;
        }
        __syncthreads();
#pragma unroll
        for (int k = 0; k < 32; k++) {
            int m = k >> 2;
            int pb = (ty ^ m) & 15;
            const ulonglong2* pA = (const ulonglong2*)&XsT[k * 132 + pb * 8];
            ulonglong2 lo = pA[0];
            ulonglong2 hi = pA[1];
            if (k & 16) { ulonglong2 tsw = lo; lo = hi; hi = tsw; }
            float4 bv = *(float4*)&Ws[k][tx * 4];
            unsigned long long bx = pack2(bv.x, bv.x);
            unsigned long long by = pack2(bv.y, bv.y);
            unsigned long long bz = pack2(bv.z, bv.z);
            unsigned long long bw = pack2(bv.w, bv.w);
            accP[0][0] = fma2v(lo.x, bx, accP[0][0]);
            accP[0][1] = fma2v(lo.x, by, accP[0][1]);
            accP[0][2] = fma2v(lo.x, bz, accP[0][2]);
            accP[0][3] = fma2v(lo.x, bw, accP[0][3]);
            accP[1][0] = fma2v(lo.y, bx, accP[1][0]);
            accP[1][1] = fma2v(lo.y, by, accP[1][1]);
            accP[1][2] = fma2v(lo.y, bz, accP[1][2]);
            accP[1][3] = fma2v(lo.y, bw, accP[1][3]);
            accP[2][0] = fma2v(hi.x, bx, accP[2][0]);
            accP[2][1] = fma2v(hi.x, by, accP[2][1]);
            accP[2][2] = fma2v(hi.x, bz, accP[2][2]);
            accP[2][3] = fma2v(hi.x, bw, accP[2][3]);
            accP[3][0] = fma2v(hi.y, bx, accP[3][0]);
            accP[3][1] = fma2v(hi.y, by, accP[3][1]);
            accP[3][2] = fma2v(hi.y, bz, accP[3][2]);
            accP[3][3] = fma2v(hi.y, bw, accP[3][3]);
        }
        __syncthreads();
    }
    float4 bias = *(const float4*)(bb + colbase + tx * 4);
#pragma unroll
    for (int p = 0; p < 4; p++) {
        float e0[4], e1[4];
#pragma unroll
        for (int j = 0; j < 4; j++) unpack2(accP[p][j], e0[j], e1[j]);
        int row = r0 + ty * 8 + 2 * p;
#pragma unroll
        for (int h = 0; h < 2; h++) {
            int rr = row + h;
            if (rr < NN) {
                const float* ev = h ? e1 : e0;
                float4 o = {ev[0] + bias.x, ev[1] + bias.y, ev[2] + bias.z, ev[3] + bias.w};
                if (HOUT && first) {
                    __half2 h01 = __floats2half2_rn(o.x, o.y);
                    __half2 h23 = __floats2half2_rn(o.z, o.w);
                    __half2* pp = (__half2*)(Y1h + (size_t)rr * kout + colbase + tx * 4);
                    pp[0] = h01; pp[1] = h23;
                } else {
                    float* Y = first ? Y1 : Y2;
                    *(float4*)(Y + (size_t)rr * kout + colbase + tx * 4) = o;
                }
            }
        }
    }
}

// ---------------- fused GATv2 aggregation + BN stats: warp/node, 4-edge batch ----
__device__ __forceinline__ void xl1_load(int s, int c0, float4& f) {
    uint2 raw = *(const uint2*)(g_xl1h + (size_t)s * HID + c0);
    float2 f01 = __half22float2(*(__half2*)&raw.x);
    float2 f23 = __half22float2(*(__half2*)&raw.y);
    f.x = f01.x; f.y = f01.y; f.z = f23.x; f.w = f23.y;
}

__global__ void k_agg1(const float* __restrict__ We, const float* __restrict__ att) {
    __shared__ float ssum[HID], ssq[HID];
    int t = threadIdx.x;
    if (t < HID) { ssum[t] = 0.f; ssq[t] = 0.f; }
    __syncthreads();
    int n = (blockIdx.x * blockDim.x + t) >> 5;
    int lane = t & 31;
    int start = g_rowstart[n];
    int end = start + g_ideg[n] + 1;
    int c0 = lane * 4;
    float4 xr = *(const float4*)(g_xr1 + (size_t)n * HID + c0);
    float4 we = *(const float4*)(We + c0);
    int h = lane >> 2;
    float4 at = *(const float4*)(att + h * C1 + (lane & 3) * 4);
    float4 numA = {0.f, 0.f, 0.f, 0.f}, numB = {0.f, 0.f, 0.f, 0.f};
    float denA = 0.f, denB = 0.f;
    int e = start;
    for (; e + 3 < end; e += 4) {
        int2 e0 = g_edge[e], e1 = g_edge[e + 1], e2i = g_edge[e + 2], e3i = g_edge[e + 3];
        float a0 = __int_as_float(e0.y), a1 = __int_as_float(e1.y);
        float a2 = __int_as_float(e2i.y), a3 = __int_as_float(e3i.y);
        float4 x0, x1, x2, x3;
        xl1_load(e0.x, c0, x0);
        xl1_load(e1.x, c0, x1);
        xl1_load(e2i.x, c0, x2);
        xl1_load(e3i.x, c0, x3);
        float u0, u1, u2, u3;
        u0 = x0.x + xr.x + a0 * we.x; u0 = u0 > 0.f ? u0 : SLOPE * u0;
        u1 = x0.y + xr.y + a0 * we.y; u1 = u1 > 0.f ? u1 : SLOPE * u1;
        u2 = x0.z + xr.z + a0 * we.z; u2 = u2 > 0.f ? u2 : SLOPE * u2;
        u3 = x0.w + xr.w + a0 * we.w; u3 = u3 > 0.f ? u3 : SLOPE * u3;
        float p0 = u0 * at.x + u1 * at.y + u2 * at.z + u3 * at.w;
        u0 = x1.x + xr.x + a1 * we.x; u0 = u0 > 0.f ? u0 : SLOPE * u0;
        u1 = x1.y + xr.y + a1 * we.y; u1 = u1 > 0.f ? u1 : SLOPE * u1;
        u2 = x1.z + xr.z + a1 * we.z; u2 = u2 > 0.f ? u2 : SLOPE * u2;
        u3 = x1.w + xr.w + a1 * we.w; u3 = u3 > 0.f ? u3 : SLOPE * u3;
        float p1 = u0 * at.x + u1 * at.y + u2 * at.z + u3 * at.w;
        u0 = x2.x + xr.x + a2 * we.x; u0 = u0 > 0.f ? u0 : SLOPE * u0;
        u1 = x2.y + xr.y + a2 * we.y; u1 = u1 > 0.f ? u1 : SLOPE * u1;
        u2 = x2.z + xr.z + a2 * we.z; u2 = u2 > 0.f ? u2 : SLOPE * u2;
        u3 = x2.w + xr.w + a2 * we.w; u3 = u3 > 0.f ? u3 : SLOPE * u3;
        float p2 = u0 * at.x + u1 * at.y + u2 * at.z + u3 * at.w;
        u0 = x3.x + xr.x + a3 * we.x; u0 = u0 > 0.f ? u0 : SLOPE * u0;
        u1 = x3.y + xr.y + a3 * we.y; u1 = u1 > 0.f ? u1 : SLOPE * u1;
        u2 = x3.z + xr.z + a3 * we.z; u2 = u2 > 0.f ? u2 : SLOPE * u2;
        u3 = x3.w + xr.w + a3 * we.w; u3 = u3 > 0.f ? u3 : SLOPE * u3;
        float p3 = u0 * at.x + u1 * at.y + u2 * at.z + u3 * at.w;
        p0 += __shfl_xor_sync(0xffffffffu, p0, 1);
        p1 += __shfl_xor_sync(0xffffffffu, p1, 1);
        p2 += __shfl_xor_sync(0xffffffffu, p2, 1);
        p3 += __shfl_xor_sync(0xffffffffu, p3, 1);
        p0 += __shfl_xor_sync(0xffffffffu, p0, 2);
        p1 += __shfl_xor_sync(0xffffffffu, p1, 2);
        p2 += __shfl_xor_sync(0xffffffffu, p2, 2);
        p3 += __shfl_xor_sync(0xffffffffu, p3, 2);
        float w0 = __expf(p0), w1 = __expf(p1), w2 = __expf(p2), w3 = __expf(p3);
        denA += w0 + w2; denB += w1 + w3;
        numA.x = fmaf(w0, x0.x, fmaf(w2, x2.x, numA.x));
        numA.y = fmaf(w0, x0.y, fmaf(w2, x2.y, numA.y));
        numA.z = fmaf(w0, x0.z, fmaf(w2, x2.z, numA.z));
        numA.w = fmaf(w0, x0.w, fmaf(w2, x2.w, numA.w));
        numB.x = fmaf(w1, x1.x, fmaf(w3, x3.x, numB.x));
        numB.y = fmaf(w1, x1.y, fmaf(w3, x3.y, numB.y));
        numB.z = fmaf(w1, x1.z, fmaf(w3, x3.z, numB.z));
        numB.w = fmaf(w1, x1.w, fmaf(w3, x3.w, numB.w));
    }
    for (; e < end; e++) {
        int2 er = g_edge[e];
        float a0 = __int_as_float(er.y);
        float4 x0; xl1_load(er.x, c0, x0);
        float u0, u1, u2, u3;
        u0 = x0.x + xr.x + a0 * we.x; u0 = u0 > 0.f ? u0 : SLOPE * u0;
        u1 = x0.y + xr.y + a0 * we.y; u1 = u1 > 0.f ? u1 : SLOPE * u1;
        u2 = x0.z + xr.z + a0 * we.z; u2 = u2 > 0.f ? u2 : SLOPE * u2;
        u3 = x0.w + xr.w + a0 * we.w; u3 = u3 > 0.f ? u3 : SLOPE * u3;
        float p0 = u0 * at.x + u1 * at.y + u2 * at.z + u3 * at.w;
        p0 += __shfl_xor_sync(0xffffffffu, p0, 1);
        p0 += __shfl_xor_sync(0xffffffffu, p0, 2);
        float w0 = __expf(p0);
        denA += w0;
        numA.x = fmaf(w0, x0.x, numA.x); numA.y = fmaf(w0, x0.y, numA.y);
        numA.z = fmaf(w0, x0.z, numA.z); numA.w = fmaf(w0, x0.w, numA.w);
    }
    float inv = 1.f / (denA + denB);
    float4 o = {(numA.x + numB.x) * inv, (numA.y + numB.y) * inv,
                (numA.z + numB.z) * inv, (numA.w + numB.w) * inv};
    *(float4*)(g_out1 + (size_t)n * HID + c0) = o;
    atomicAdd(&ssum[c0 + 0], o.x); atomicAdd(&ssq[c0 + 0], o.x * o.x);
    atomicAdd(&ssum[c0 + 1], o.y); atomicAdd(&ssq[c0 + 1], o.y * o.y);
    atomicAdd(&ssum[c0 + 2], o.z); atomicAdd(&ssq[c0 + 2], o.z * o.z);
    atomicAdd(&ssum[c0 + 3], o.w); atomicAdd(&ssq[c0 + 3], o.w * o.w);
    __syncthreads();
    if (t < HID) { atomicAdd(&g_bnsum[t], ssum[t]); atomicAdd(&g_bnsq[t], ssq[t]); }
}

__global__ void k_agg2(const float* __restrict__ We, const float* __restrict__ att) {
    __shared__ float ssum[EMB], ssq[EMB];
    int t = threadIdx.x;
    if (t < EMB) { ssum[t] = 0.f; ssq[t] = 0.f; }
    __syncthreads();
    int n = (blockIdx.x * blockDim.x + t) >> 5;
    int lane = t & 31;
    int start = g_rowstart[n];
    int end = start + g_ideg[n] + 1;
    int c0 = lane * 2;
    float2 xr = *(const float2*)(g_xr2 + (size_t)n * EMB + c0);
    float2 we = *(const float2*)(We + c0);
    float2 at = *(const float2*)(att + c0);
    float2 numA = {0.f, 0.f}, numB = {0.f, 0.f};
    float denA = 0.f, denB = 0.f;
    int e = start;
    for (; e + 3 < end; e += 4) {
        int2 e0 = g_edge[e], e1 = g_edge[e + 1], e2i = g_edge[e + 2], e3i = g_edge[e + 3];
        float a0 = __int_as_float(e0.y), a1 = __int_as_float(e1.y);
        float a2 = __int_as_float(e2i.y), a3 = __int_as_float(e3i.y);
        float2 x0 = *(const float2*)(g_xl2 + (size_t)e0.x * EMB + c0);
        float2 x1 = *(const float2*)(g_xl2 + (size_t)e1.x * EMB + c0);
        float2 x2 = *(const float2*)(g_xl2 + (size_t)e2i.x * EMB + c0);
        float2 x3 = *(const float2*)(g_xl2 + (size_t)e3i.x * EMB + c0);
        float u0, u1;
        u0 = x0.x + xr.x + a0 * we.x; u0 = u0 > 0.f ? u0 : SLOPE * u0;
        u1 = x0.y + xr.y + a0 * we.y; u1 = u1 > 0.f ? u1 : SLOPE * u1;
        float p0 = u0 * at.x + u1 * at.y;
        u0 = x1.x + xr.x + a1 * we.x; u0 = u0 > 0.f ? u0 : SLOPE * u0;
        u1 = x1.y + xr.y + a1 * we.y; u1 = u1 > 0.f ? u1 : SLOPE * u1;
        float p1 = u0 * at.x + u1 * at.y;
        u0 = x2.x + xr.x + a2 * we.x; u0 = u0 > 0.f ? u0 : SLOPE * u0;
        u1 = x2.y + xr.y + a2 * we.y; u1 = u1 > 0.f ? u1 : SLOPE * u1;
        float p2 = u0 * at.x + u1 * at.y;
        u0 = x3.x + xr.x + a3 * we.x; u0 = u0 > 0.f ? u0 : SLOPE * u0;
        u1 = x3.y + xr.y + a3 * we.y; u1 = u1 > 0.f ? u1 : SLOPE * u1;
        float p3 = u0 * at.x + u1 * at.y;
#pragma unroll
        for (int off = 16; off > 0; off >>= 1) {
            p0 += __shfl_xor_sync(0xffffffffu, p0, off);
            p1 += __shfl_xor_sync(0xffffffffu, p1, off);
            p2 += __shfl_xor_sync(0xffffffffu, p2, off);
            p3 += __shfl_xor_sync(0xffffffffu, p3, off);
        }
        float w0 = __expf(p0), w1 = __expf(p1), w2 = __expf(p2), w3 = __expf(p3);
        denA += w0 + w2; denB += w1 + w3;
        numA.x = fmaf(w0, x0.x, fmaf(w2, x2.x, numA.x));
        numA.y = fmaf(w0, x0.y, fmaf(w2, x2.y, numA.y));
        numB.x = fmaf(w1, x1.x, fmaf(w3, x3.x, numB.x));
        numB.y = fmaf(w1, x1.y, fmaf(w3, x3.y, numB.y));
    }
    for (; e < end; e++) {
        int2 er = g_edge[e];
        float a0 = __int_as_float(er.y);
        float2 x0 = *(const float2*)(g_xl2 + (size_t)er.x * EMB + c0);
        float u0, u1;
        u0 = x0.x + xr.x + a0 * we.x; u0 = u0 > 0.f ? u0 : SLOPE * u0;
        u1 = x0.y + xr.y + a0 * we.y; u1 = u1 > 0.f ? u1 : SLOPE * u1;
        float p0 = u0 * at.x + u1 * at.y;
#pragma unroll
        for (int off = 16; off > 0; off >>= 1)
            p0 += __shfl_xor_sync(0xffffffffu, p0, off);
        float w0 = __expf(p0);
        denA += w0;
        numA.x = fmaf(w0, x0.x, numA.x); numA.y = fmaf(w0, x0.y, numA.y);
    }
    float inv = 1.f / (denA + denB);
    float2 o = {(numA.x + numB.x) * inv, (numA.y + numB.y) * inv};
    *(float2*)(g_out2 + (size_t)n * EMB + c0) = o;
    atomicAdd(&ssum[c0 + 0], o.x); atomicAdd(&ssq[c0 + 0], o.x * o.x);
    atomicAdd(&ssum[c0 + 1], o.y); atomicAdd(&ssq[c0 + 1], o.y * o.y);
    __syncthreads();
    if (t < EMB) { atomicAdd(&g_bnsum2[t], ssum[t]); atomicAdd(&g_bnsq2[t], ssq[t]); }
}

// BN2(inline) + relu + node_emb + pooled sums; last block finishes pool+logits
__global__ void k_bnapply2(const float* __restrict__ Yin, float* __restrict__ out,
                           const int* __restrict__ batch,
                           const float* __restrict__ gamma, const float* __restrict__ beta,
                           const float* __restrict__ Wc, const float* __restrict__ bc) {
    int i = blockIdx.x * 256 + threadIdx.x;   // grid covers NN*EMB exactly
    int c = i & (EMB - 1);
    int node = i >> 6;
    float mu = g_bnsum2[c] * (1.f / NN);
    float var = g_bnsq2[c] * (1.f / NN) - mu * mu;
    float sc = gamma[c] * rsqrtf(var + EPSV);
    float v = fmaf(Yin[i] - mu, sc, beta[c]);
    v = fmaxf(v, 0.f);
    out[NCLS * GG + GG * EMB + i] = v;        // node_emb
    atomicAdd(&g_pool[batch[node] * EMB + c], v);

    __threadfence();
    __shared__ int lastblk;
    __shared__ float sdom[GG * EMB];
    if (threadIdx.x == 0)
        lastblk = (atomicAdd(&g_done, 1) == (NN * EMB) / 256 - 1);
    __syncthreads();
    if (!lastblk) return;
    for (int p = threadIdx.x; p < GG * EMB; p += 256) {
        int g = p >> 6;
        float dm = g_pool[p] / fmaxf(g_cnt[g], 1.f);
        sdom[p] = dm;
        out[NCLS * GG + p] = dm;              // domain_emb
    }
    __syncthreads();
    for (int p = threadIdx.x; p < GG * NCLS; p += 256) {
        int g = p / NCLS, cc = p % NCLS;
        float acc = bc[cc];
#pragma unroll 8
        for (int k = 0; k < EMB; k++)
            acc = fmaf(sdom[g * EMB + k], Wc[k * NCLS + cc], acc);
        out[p] = acc;                          // logits
    }
}

// ---------------- host ----------------
extern "C" void kernel_launch(void* const* d_in, const int* in_sizes, int n_in,
                              void* d_out, int out_size) {
    const float* x     = (const float*)d_in[0];
    const int*   ei    = (const int*)d_in[1];
    const float* eattr = (const float*)d_in[2];
    const int*   batch = (const int*)d_in[3];
    const float* Wl1 = (const float*)d_in[4];  const float* bl1 = (const float*)d_in[5];
    const float* Wr1 = (const float*)d_in[6];  const float* br1 = (const float*)d_in[7];
    const float* We1 = (const float*)d_in[8];  const float* att1 = (const float*)d_in[9];
    // bias1 (d_in[10]) cancels exactly through BN1 -> skipped
    const float* Wl2 = (const float*)d_in[11]; const float* bl2 = (const float*)d_in[12];
    const float* Wr2 = (const float*)d_in[13]; const float* br2 = (const float*)d_in[14];
    const float* We2 = (const float*)d_in[15]; const float* att2 = (const float*)d_in[16];
    // bias2 (d_in[17]) cancels through BN2 -> skipped
    const float* gamma1 = (const float*)d_in[18]; const float* beta1 = (const float*)d_in[19];
    const float* gamma2 = (const float*)d_in[20]; const float* beta2 = (const float*)d_in[21];
    const float* Wc = (const float*)d_in[22]; const float* bc = (const float*)d_in[23];
    float* out = (float*)d_out;

    float *xr1, *out1, *xl2, *xr2, *out2;
    __half* xl1h;
    cudaGetSymbolAddress((void**)&xl1h, g_xl1h);
    cudaGetSymbolAddress((void**)&xr1, g_xr1);
    cudaGetSymbolAddress((void**)&out1, g_out1);
    cudaGetSymbolAddress((void**)&xl2, g_xl2);
    cudaGetSymbolAddress((void**)&xr2, g_xr2);
    cudaGetSymbolAddress((void**)&out2, g_out2);

    const int* src = ei;
    const int* dst = ei + EE;

    bool par = (g_side != nullptr);

    // ---- fork: gemm1 runs concurrent with CSR build ----
    if (par) {
        cudaEventRecord(g_evF, 0);
        cudaStreamWaitEvent(g_side, g_evF, 0);
    }
    k_gemm<FIN, false, true><<<dim3(391, 4), 256, 0, par ? g_side : 0>>>(
        x, Wl1, bl1, nullptr, xl1h, Wr1, br1, xr1, HID, 2, nullptr, nullptr);
    if (par) cudaEventRecord(g_evJ, g_side);

    // ---- CSR build (main stream, multi-block scan) ----
    k_zero<<<NB, 256>>>();
    k_hist<<<(EE + 255) / 256, 256>>>(dst, eattr);
    k_scanA<<<NB, 256>>>();
    k_scanB<<<1, 256>>>();
    k_scanC<<<NB, 256>>>(batch);
    k_scatterE<<<(EE + 255) / 256, 256>>>(src, dst, eattr);

    // ---- join ----
    if (par) cudaStreamWaitEvent(0, g_evJ, 0);

    // ---- layer 1 aggregation (+BN1 stats) ----
    k_agg1<<<6250, 256>>>(We1, att1);

    // ---- layer 2 (BN1+relu fused into GEMM X load) ----
    k_gemm<HID, true, false><<<dim3(391, 2), 256>>>(
        out1, Wl2, bl2, xl2, nullptr, Wr2, br2, xr2, EMB, 1, gamma1, beta1);
    k_agg2<<<6250, 256>>>(We2, att2);

    // ---- BN2 + pooling + classifier (fused tail) ----
    k_bnapply2<<<(NN * EMB) / 256, 256>>>(out2, out, batch, gamma2, beta2, Wc, bc);
}